// round 16
// baseline (speedup 1.0000x reference)
#include <cuda_runtime.h>
#include <cuda_fp16.h>
#include <cstdint>

// ======================= config =======================
#define BM 128
#define BN 256
#define BK 64                    // fp16 elems per K-chunk: 64*2B = 128B rows
#define STAGES 4

static constexpr int KDIM   = 4096;
static constexpr int NDIM   = 4096;
static constexpr int MMAX   = 8192;
static constexpr int KITERS = KDIM / BK;   // 64

#define A_BYTES     (BM * 128)             // 16384
#define B_BYTES     (BN * 128)             // 32768
#define STAGE_BYTES (A_BYTES + B_BYTES)    // 49152
#define SMEM_TOTAL  (STAGES * STAGE_BYTES) // 196608

// scratch (allocation-free rule: __device__ globals)
__device__ __align__(1024) __half g_xh[(size_t)MMAX * KDIM];  // 64 MiB
__device__ __align__(1024) __half g_wh[(size_t)NDIM * KDIM];  // 32 MiB

// ======================= PTX helpers =======================
__device__ __forceinline__ uint32_t smem_u32(const void* p) {
    uint32_t a;
    asm("{ .reg .u64 t; cvta.to.shared.u64 t, %1; cvt.u32.u64 %0, t; }" : "=r"(a) : "l"(p));
    return a;
}

#define CP_ASYNC16(dst, src) \
    asm volatile("cp.async.cg.shared.global [%0], [%1], 16;" :: "r"(dst), "l"(src) : "memory")
#define CP_COMMIT() asm volatile("cp.async.commit_group;" ::: "memory")
#define CP_WAIT(n)  asm volatile("cp.async.wait_group %0;" :: "n"(n) : "memory")

#define LDSM4(r, addr) \
    asm volatile("ldmatrix.sync.aligned.m8n8.x4.shared.b16 {%0,%1,%2,%3}, [%4];" \
        : "=r"((r)[0]), "=r"((r)[1]), "=r"((r)[2]), "=r"((r)[3]) : "r"(addr))

// f16 x f16 -> f16 accumulate (2x pipe rate vs f32-acc, measured R7)
#define MMA16816_F16(d, a, b0, b1) \
    asm volatile("mma.sync.aligned.m16n8k16.row.col.f16.f16.f16.f16 " \
        "{%0,%1},{%2,%3,%4,%5},{%6,%7},{%0,%1};" \
        : "+r"((d)[0]), "+r"((d)[1]) \
        : "r"((a)[0]), "r"((a)[1]), "r"((a)[2]), "r"((a)[3]), "r"(b0), "r"(b1))

// swizzled smem byte offset: 128B rows, 8x16B chunks, chunk XOR row&7
__device__ __forceinline__ uint32_t swz(int row, int chunk) {
    return (uint32_t)(row * 128 + ((chunk ^ (row & 7)) << 4));
}

// ======================= preprocessing (merged kernel keeps ncu on the GEMM) ===
__global__ void convert_xw_kernel(const float* __restrict__ x,
                                  const int* __restrict__ q,
                                  __half* __restrict__ xh,
                                  __half* __restrict__ wh,
                                  int n4x, int n4w) {
    const int stride = gridDim.x * blockDim.x;
    for (int i = blockIdx.x * blockDim.x + threadIdx.x; i < n4x; i += stride) {
        float4 v = reinterpret_cast<const float4*>(x)[i];
        __half2 h0 = __floats2half2_rn(v.x, v.y);
        __half2 h1 = __floats2half2_rn(v.z, v.w);
        uint2 pk;
        pk.x = *reinterpret_cast<uint32_t*>(&h0);
        pk.y = *reinterpret_cast<uint32_t*>(&h1);
        reinterpret_cast<uint2*>(xh)[i] = pk;
    }
    for (int i = blockIdx.x * blockDim.x + threadIdx.x; i < n4w; i += stride) {
        int4 v = reinterpret_cast<const int4*>(q)[i];
        // q in [0,127): exact in fp16
        __half2 h0 = __floats2half2_rn((float)v.x, (float)v.y);
        __half2 h1 = __floats2half2_rn((float)v.z, (float)v.w);
        uint2 pk;
        pk.x = *reinterpret_cast<uint32_t*>(&h0);
        pk.y = *reinterpret_cast<uint32_t*>(&h1);
        reinterpret_cast<uint2*>(wh)[i] = pk;
    }
}

// ======================= GEMM =======================
__device__ __forceinline__ void load_stage(uint32_t sb, int s, int kn, int tid,
                                           const __half* Ag, const __half* Bg) {
    const uint32_t base = sb + (uint32_t)s * STAGE_BYTES;
    const int row = tid >> 3;          // 0..31
    const int c   = tid & 7;           // 16B chunk
    const int kcol = kn * BK + c * 8;  // fp16 column
    #pragma unroll
    for (int it = 0; it < BM / 32; it++) {          // A: 128 rows
        const int r = row + it * 32;
        CP_ASYNC16(base + swz(r, c), Ag + (size_t)r * KDIM + kcol);
    }
    #pragma unroll
    for (int it = 0; it < BN / 32; it++) {          // B: 256 rows
        const int r = row + it * 32;
        CP_ASYNC16(base + A_BYTES + swz(r, c), Bg + (size_t)r * KDIM + kcol);
    }
    CP_COMMIT();
}

// one k-iteration; GRP in [0,4) selects the QUARTER of tiles (nt pair) that
// drains this iter. Each f16 chain therefore spans 4 k-iters = K=256.
// (calibrated error: chain term ~6e-4, total ~6.3e-4 < 1e-3)
#define ITER_BODY(KN, GRP) do {                                                      \
    const uint32_t abase = sb + (uint32_t)((KN) & 3) * STAGE_BYTES;                  \
    const uint32_t bbase = abase + A_BYTES;                                          \
    /* ks0: fragments already prefetched last iteration */                           \
    _Pragma("unroll")                                                                \
    for (int mt = 0; mt < 4; mt++)                                                   \
        _Pragma("unroll")                                                            \
        for (int nt = 0; nt < 8; nt++) {                                             \
            const int bi = nt >> 1, sel = nt & 1;                                    \
            MMA16816_F16(acch[mt][nt], a[mt], b[bi][sel], b[bi][sel + 2]);           \
        }                                                                            \
    /* ks = 1..3 */                                                                  \
    _Pragma("unroll")                                                                \
    for (int ks = 1; ks < 4; ks++) {                                                 \
        const int kc = ks * 2 + chi;                                                 \
        _Pragma("unroll")                                                            \
        for (int mt = 0; mt < 4; mt++)                                               \
            LDSM4(a[mt], abase + swz(arow0 + mt * 16, kc));                          \
        _Pragma("unroll")                                                            \
        for (int bi = 0; bi < 4; bi++)                                               \
            LDSM4(b[bi], bbase + swz(brow0 + bi * 16, kc));                          \
        _Pragma("unroll")                                                            \
        for (int mt = 0; mt < 4; mt++)                                               \
            _Pragma("unroll")                                                        \
            for (int nt = 0; nt < 8; nt++) {                                         \
                const int bi = nt >> 1, sel = nt & 1;                                \
                MMA16816_F16(acch[mt][nt], a[mt], b[bi][sel], b[bi][sel + 2]);       \
            }                                                                        \
    }                                                                                \
    /* next-stage copy into slot (KN+3)&3 (reads confirmed by prev barrier) */      \
    if ((KN) + STAGES - 1 < KITERS)                                                  \
        load_stage(sb, ((KN) + STAGES - 1) & 3, (KN) + STAGES - 1, tid, Ag, Bg);     \
    else                                                                             \
        CP_COMMIT();                                                                 \
    /* prefetch ks0 of stage KN+1 (visible since prev barrier) */                    \
    {                                                                                \
        const uint32_t nabase = sb + (uint32_t)(((KN) + 1) & 3) * STAGE_BYTES;       \
        const uint32_t nbbase = nabase + A_BYTES;                                    \
        _Pragma("unroll")                                                            \
        for (int mt = 0; mt < 4; mt++)                                               \
            LDSM4(a[mt], nabase + swz(arow0 + mt * 16, chi));                        \
        _Pragma("unroll")                                                            \
        for (int bi = 0; bi < 4; bi++)                                               \
            LDSM4(b[bi], nbbase + swz(brow0 + bi * 16, chi));                        \
    }                                                                                \
    /* drain ONE QUARTER of the tiles (chains span 4 k-iters = K=256) */            \
    _Pragma("unroll")                                                                \
    for (int mt = 0; mt < 4; mt++)                                                   \
        _Pragma("unroll")                                                            \
        for (int nt = (GRP) * 2; nt < (GRP) * 2 + 2; nt++) {                         \
            const float2 f0 = __half22float2(*reinterpret_cast<__half2*>(&acch[mt][nt][0])); \
            const float2 f1 = __half22float2(*reinterpret_cast<__half2*>(&acch[mt][nt][1])); \
            accf[mt][nt][0] += f0.x;                                                 \
            accf[mt][nt][1] += f0.y;                                                 \
            accf[mt][nt][2] += f1.x;                                                 \
            accf[mt][nt][3] += f1.y;                                                 \
            acch[mt][nt][0] = 0u;                                                    \
            acch[mt][nt][1] = 0u;                                                    \
        }                                                                            \
    CP_WAIT(1);                                                                      \
    __syncthreads();                                                                 \
} while (0)

__global__ void __launch_bounds__(256, 1) qlinear_gemm(
    float* __restrict__ out,
    const float* __restrict__ scale,
    const float* __restrict__ bias,
    const __half* __restrict__ Agbase,
    const __half* __restrict__ Bgbase)
{
    extern __shared__ char smem[];
    const uint32_t sb = smem_u32(smem);
    const int tid  = threadIdx.x;
    const int warp = tid >> 5;
    const int lane = tid & 31;
    const int wm   = warp >> 2;        // 0..1  (64-row slab)
    const int wn   = warp & 3;         // 0..3  (64-col slab)
    const int bn   = blockIdx.x;
    const int bm   = blockIdx.y;

    const __half* Ag = Agbase + (size_t)bm * BM * KDIM;
    const __half* Bg = Bgbase + (size_t)bn * BN * KDIM;

    // prologue: fill STAGES-1 stages
    #pragma unroll
    for (int s = 0; s < STAGES - 1; s++) load_stage(sb, s, s, tid, Ag, Bg);

    // f32 masters + f16 chain accumulators
    float accf[4][8][4];
    uint32_t acch[4][8][2];
    #pragma unroll
    for (int mt = 0; mt < 4; mt++)
        #pragma unroll
        for (int nt = 0; nt < 8; nt++) {
            #pragma unroll
            for (int j = 0; j < 4; j++) accf[mt][nt][j] = 0.f;
            acch[mt][nt][0] = 0u;
            acch[mt][nt][1] = 0u;
        }

    const int arow0 = wm * 64 + (lane & 15);
    const int brow0 = wn * 64 + (lane & 15);
    const int chi   = lane >> 4;       // 0/1: k8-chunk within k16

    // single-buffered fragments, live across the barrier (pipelined ks0)
    uint32_t a[4][4], b[4][4];

    // prologue sync: stages 0 AND 1 visible (wait(1): done >= 2 groups)
    CP_WAIT(1);
    __syncthreads();

    // prefetch ks0 fragments of stage 0
    #pragma unroll
    for (int mt = 0; mt < 4; mt++)
        LDSM4(a[mt], sb + swz(arow0 + mt * 16, chi));
    #pragma unroll
    for (int bi = 0; bi < 4; bi++)
        LDSM4(b[bi], sb + A_BYTES + swz(brow0 + bi * 16, chi));

    for (int kn4 = 0; kn4 < KITERS; kn4 += 4) {
        ITER_BODY(kn4,     0);   // drain nt 0..1
        ITER_BODY(kn4 + 1, 1);   // drain nt 2..3
        ITER_BODY(kn4 + 2, 2);   // drain nt 4..5
        ITER_BODY(kn4 + 3, 3);   // drain nt 6..7
    }

    // final drain: groups 0..2 still hold tail iters (group 3 holds zeros)
    #pragma unroll
    for (int mt = 0; mt < 4; mt++)
        #pragma unroll
        for (int nt = 0; nt < 8; nt++) {
            const float2 f0 = __half22float2(*reinterpret_cast<__half2*>(&acch[mt][nt][0]));
            const float2 f1 = __half22float2(*reinterpret_cast<__half2*>(&acch[mt][nt][1]));
            accf[mt][nt][0] += f0.x;
            accf[mt][nt][1] += f0.y;
            accf[mt][nt][2] += f1.x;
            accf[mt][nt][3] += f1.y;
        }

    // ---------- epilogue: y = accf*scale + bias ----------
    const float sc = scale[0];
    const int qrow = lane >> 2;          // 0..7
    const int qcol = (lane & 3) * 2;     // 0,2,4,6

    #pragma unroll
    for (int mt = 0; mt < 4; mt++) {
        const int row = bm * BM + wm * 64 + mt * 16 + qrow;
        #pragma unroll
        for (int nt = 0; nt < 8; nt++) {
            const int col = bn * BN + wn * 64 + nt * 8 + qcol;
            const float b0 = bias[col], b1 = bias[col + 1];
            float2 v0, v1;
            v0.x = accf[mt][nt][0] * sc + b0;
            v0.y = accf[mt][nt][1] * sc + b1;
            v1.x = accf[mt][nt][2] * sc + b0;
            v1.y = accf[mt][nt][3] * sc + b1;
            *reinterpret_cast<float2*>(out + (size_t)row * NDIM + col) = v0;
            *reinterpret_cast<float2*>(out + (size_t)(row + 8) * NDIM + col) = v1;
        }
    }
}

// ======================= host launch =======================
extern "C" void kernel_launch(void* const* d_in, const int* in_sizes, int n_in,
                              void* d_out, int out_size) {
    const float* x  = (const float*)d_in[0];
    const int*   qw = (const int*)d_in[1];
    const float* sc = (const float*)d_in[2];
    const float* bs = (const float*)d_in[3];
    float* out = (float*)d_out;

    const int M = in_sizes[0] / KDIM;   // 8192

    void *p_xh = nullptr, *p_wh = nullptr;
    cudaGetSymbolAddress(&p_xh, g_xh);
    cudaGetSymbolAddress(&p_wh, g_wh);

    convert_xw_kernel<<<2048, 256>>>(x, qw, (__half*)p_xh, (__half*)p_wh,
                                     (M * KDIM) / 4, (NDIM * KDIM) / 4);

    static bool smem_set = false;
    if (!smem_set) {
        cudaFuncSetAttribute(qlinear_gemm, cudaFuncAttributeMaxDynamicSharedMemorySize, SMEM_TOTAL);
        smem_set = true;
    }
    dim3 grid(NDIM / BN, M / BM);   // (16, 64): bn fastest -> A-row reuse in L2
    qlinear_gemm<<<grid, 256, SMEM_TOTAL>>>(out, sc, bs,
        (const __half*)p_xh, (const __half*)p_wh);
}